// round 15
// baseline (speedup 1.0000x reference)
#include <cuda_runtime.h>
#include <cuda_bf16.h>
#include <math.h>
#include <stdint.h>

#define N_     256
#define M_     50000
#define K_     3072
#define KT     128            // fp8 k-values per tile (128B rows, classic SW128)
#define NT1    (K_ / KT)      // 24
#define NTILE  391            // ceil(M/128)
#define INV_VAR 4.0f
#define HMAX   160
#define LMAX   128
#define THRESH 175.0f         // 30 (softmax) + 2*68 (e4m3 score err 6sigma) + 9 (bf16 store)
#define STG    49152          // stage: A 16K | B 32K
#define NSTG   3

// ---------------- device scratch (allocation-free) ----------------
__device__ __align__(128) __nv_bfloat16  g_scores[(size_t)M_ * N_];
__device__ __align__(128) unsigned char  g_Xq[(size_t)N_ * K_];
__device__ __align__(128) float          g_tmax[(size_t)NTILE * N_];
__device__ unsigned int g_gmax_u[N_];

// ---------------- helpers ----------------
__device__ __forceinline__ uint32_t s2u(const void* p) {
    return (uint32_t)__cvta_generic_to_shared(p);
}
// 128B rows, classic SW128: chunk c (16B) XOR row&7
__device__ __forceinline__ uint32_t soff64(uint32_t r, uint32_t c) {
    return (r << 7) + ((c ^ (r & 7)) << 4);
}
__device__ __forceinline__ void cp16(uint32_t dst, const void* src) {
    asm volatile("cp.async.cg.shared.global [%0], [%1], 16;" :: "r"(dst), "l"(src));
}
__device__ __forceinline__ void cp_commit() { asm volatile("cp.async.commit_group;"); }
__device__ __forceinline__ void cp_wait1() { asm volatile("cp.async.wait_group 1;" ::: "memory"); }
__device__ __forceinline__ void cp_wait0() { asm volatile("cp.async.wait_group 0;" ::: "memory"); }

__device__ __forceinline__ void ldsm4(uint32_t* d, uint32_t addr) {
    asm volatile("ldmatrix.sync.aligned.m8n8.x4.shared.b16 {%0,%1,%2,%3}, [%4];"
        : "=r"(d[0]), "=r"(d[1]), "=r"(d[2]), "=r"(d[3]) : "r"(addr));
}
// fp8 e4m3 MMA: D(16x8,f32) += A(16x32,e4m3) x B(32x8,e4m3)
__device__ __forceinline__ void mma_fp8(float* c, const uint32_t* a, uint32_t b0, uint32_t b1) {
    asm volatile("mma.sync.aligned.m16n8k32.row.col.f32.e4m3.e4m3.f32 "
        "{%0,%1,%2,%3}, {%4,%5,%6,%7}, {%8,%9}, {%0,%1,%2,%3};"
        : "+f"(c[0]), "+f"(c[1]), "+f"(c[2]), "+f"(c[3])
        : "r"(a[0]), "r"(a[1]), "r"(a[2]), "r"(a[3]), "r"(b0), "r"(b1));
}
__device__ __forceinline__ unsigned int fkey(float f) {
    unsigned int b = __float_as_uint(f);
    return (b & 0x80000000u) ? ~b : (b | 0x80000000u);
}
__device__ __forceinline__ float funkey(unsigned int k) {
    unsigned int b = (k & 0x80000000u) ? (k & 0x7FFFFFFFu) : ~k;
    return __uint_as_float(b);
}
__device__ __forceinline__ uint32_t pk2(float x, float y) {   // bf16(x) low, bf16(y) high
    __nv_bfloat162 t = __floats2bfloat162_rn(x, y);
    return *(uint32_t*)&t;
}
// two floats -> packed e4m3x2, low byte = lo
__device__ __forceinline__ uint16_t f2q2(float lo, float hi) {
    uint16_t r;
    asm("cvt.rn.satfinite.e4m3x2.f32 %0, %1, %2;" : "=h"(r) : "f"(hi), "f"(lo));
    return r;
}

// ---------------- X fp32 -> e4m3 (+ zero per-launch state in block 0) --------
__global__ __launch_bounds__(256)
void k_conv_x(const float* __restrict__ X) {
    if (blockIdx.x == 0) g_gmax_u[threadIdx.x] = 0u;
    size_t i = (size_t)blockIdx.x * 256 + threadIdx.x;
    if (i >= (size_t)N_ * K_ / 8) return;
    float4 a = ((const float4*)X)[2 * i];
    float4 b = ((const float4*)X)[2 * i + 1];
    unsigned long long pk =
          (unsigned long long)f2q2(a.x, a.y)
        | ((unsigned long long)f2q2(a.z, a.w) << 16)
        | ((unsigned long long)f2q2(b.x, b.y) << 32)
        | ((unsigned long long)f2q2(b.z, b.w) << 48);
    ((unsigned long long*)g_Xq)[i] = pk;
}

// ---------------- GEMM1: approx scores[m][n] = 4 * e4m3(D).e4m3(X)^T ---------
// CTA tile 128m x 256n. 8 warps = 2m x 4n, warp tile 64x64. KT=128 fp8,
// 3-stage ring (dist 2). D read once (fp32), converted to e4m3 in-register.
__global__ __launch_bounds__(256, 1)
void k_gemm1(const float* __restrict__ Dp) {
    extern __shared__ char smem[];
    const uint32_t sb = s2u(smem);
    const int tid = threadIdx.x, wid = tid >> 5, lane = tid & 31;
    const int m0 = blockIdx.x * 128;
    const int wm = (wid >> 2) * 64;        // 0 or 64
    const int wn = (wid & 3) * 64;         // 0,64,128,192

    // A loader: thread -> (row = tid>>1, half h = tid&1 covering k-bytes 64h..64h+63)
    const int arowl = tid >> 1, ah_ = tid & 1;
    int am = m0 + arowl; if (am >= M_) am = M_ - 1;
    const float* aPtrF = Dp + (size_t)am * K_ + ah_ * 64;
    uint32_t aOff[4];
    #pragma unroll
    for (int q = 0; q < 4; q++) aOff[q] = soff64(arowl, ah_ * 4 + q);

    float acc[4][8][4];
    #pragma unroll
    for (int a = 0; a < 4; a++)
        #pragma unroll
        for (int b = 0; b < 8; b++)
            #pragma unroll
            for (int q = 0; q < 4; q++) acc[a][b][q] = 0.f;

    uint4 cv[4];                                  // converted A chunk data
    auto ldgA = [&](int kt) {                     // 16 LDG.128 + cvt -> 4 uint4
        const float* p = aPtrF + (size_t)kt * KT;
        #pragma unroll
        for (int q = 0; q < 4; q++) {
            float4 v0 = *(const float4*)(p + q * 16);
            float4 v1 = *(const float4*)(p + q * 16 + 4);
            float4 v2 = *(const float4*)(p + q * 16 + 8);
            float4 v3 = *(const float4*)(p + q * 16 + 12);
            cv[q].x = (uint32_t)f2q2(v0.x, v0.y) | ((uint32_t)f2q2(v0.z, v0.w) << 16);
            cv[q].y = (uint32_t)f2q2(v1.x, v1.y) | ((uint32_t)f2q2(v1.z, v1.w) << 16);
            cv[q].z = (uint32_t)f2q2(v2.x, v2.y) | ((uint32_t)f2q2(v2.z, v2.w) << 16);
            cv[q].w = (uint32_t)f2q2(v3.x, v3.y) | ((uint32_t)f2q2(v3.z, v3.w) << 16);
        }
    };
    auto stsA = [&](int s) {
        char* st = smem + s * STG;
        #pragma unroll
        for (int q = 0; q < 4; q++)
            *(uint4*)(st + aOff[q]) = cv[q];
    };
    auto cpB = [&](int s, int kt) {
        const uint32_t st = sb + s * STG + 16384;
        const size_t k0 = (size_t)kt * KT;
        #pragma unroll
        for (int q8 = 0; q8 < 8; q8++) {
            int e = q8 * 256 + tid;
            int r = e >> 3, c = e & 7;
            cp16(st + soff64(r, c), g_Xq + (size_t)r * K_ + k0 + c * 16);
        }
        cp_commit();
    };

    ldgA(0); cpB(0, 0); stsA(0);
    ldgA(1); cpB(1, 1); stsA(1);

    for (int t = 0; t < NT1; t++) {
        const int pf = (t + 2 < NT1);
        if (pf) ldgA(t + 2);
        if (pf) cp_wait1(); else cp_wait0();
        __syncthreads();
        const int sNew = (t + 2) % NSTG;
        if (pf) cpB(sNew, t + 2);

        const uint32_t stA = sb + (t % NSTG) * STG;
        const uint32_t stB = stA + 16384;
        #pragma unroll
        for (int ks = 0; ks < 4; ks++) {          // k32 per step, chunks {2ks, 2ks+1}
            const uint32_t cc = ks * 2 + (lane >> 4);
            uint32_t ahf[4][4];
            #pragma unroll
            for (int mi = 0; mi < 4; mi++)
                ldsm4(ahf[mi], stA + soff64(wm + mi * 16 + (lane & 15), cc));
            #pragma unroll
            for (int g = 0; g < 4; g++) {
                uint32_t bh[4];
                ldsm4(bh, stB + soff64(wn + g * 16 + (lane & 15), cc));
                #pragma unroll
                for (int mi = 0; mi < 4; mi++) {
                    mma_fp8(acc[mi][g*2],   ahf[mi], bh[0], bh[2]);
                    mma_fp8(acc[mi][g*2+1], ahf[mi], bh[1], bh[3]);
                }
            }
        }
        if (pf) stsA(sNew);
    }

    // epilogue: scale, store bf16 scores, per-n maxima
    float mv0[8], mv1[8];
    #pragma unroll
    for (int mi = 0; mi < 4; mi++) {
        int m = m0 + wm + mi * 16 + (lane >> 2);
        #pragma unroll
        for (int nj = 0; nj < 8; nj++) {
            int n = wn + nj * 8 + (lane & 3) * 2;
            float v0 = acc[mi][nj][0] * INV_VAR, v1 = acc[mi][nj][1] * INV_VAR;
            float v2 = acc[mi][nj][2] * INV_VAR, v3 = acc[mi][nj][3] * INV_VAR;
            acc[mi][nj][0] = v0; acc[mi][nj][1] = v1;
            acc[mi][nj][2] = v2; acc[mi][nj][3] = v3;
            if (m < M_)     *(uint32_t*)&g_scores[(size_t)m * N_ + n]       = pk2(v0, v1);
            if (m + 8 < M_) *(uint32_t*)&g_scores[(size_t)(m + 8) * N_ + n] = pk2(v2, v3);
        }
    }
    #pragma unroll
    for (int nj = 0; nj < 8; nj++) {
        float v0 = -1e30f, v1 = -1e30f;
        #pragma unroll
        for (int mi = 0; mi < 4; mi++) {
            v0 = fmaxf(v0, fmaxf(acc[mi][nj][0], acc[mi][nj][2]));
            v1 = fmaxf(v1, fmaxf(acc[mi][nj][1], acc[mi][nj][3]));
        }
        #pragma unroll
        for (int mk = 4; mk < 32; mk <<= 1) {
            v0 = fmaxf(v0, __shfl_xor_sync(0xFFFFFFFFu, v0, mk));
            v1 = fmaxf(v1, __shfl_xor_sync(0xFFFFFFFFu, v1, mk));
        }
        mv0[nj] = v0; mv1[nj] = v1;
    }
    float* s_max = (float*)smem;          // stage-0 A region dead after final barrier
    __syncthreads();
    if (wm == 0 && (lane >> 2) == 0) {
        #pragma unroll
        for (int nj = 0; nj < 8; nj++) {
            int n = wn + nj * 8 + (lane & 3) * 2;
            s_max[n] = mv0[nj]; s_max[n + 1] = mv1[nj];
        }
    }
    __syncthreads();
    if (wm == 64 && (lane >> 2) == 0) {
        #pragma unroll
        for (int nj = 0; nj < 8; nj++) {
            int n = wn + nj * 8 + (lane & 3) * 2;
            float c0 = fmaxf(mv0[nj], s_max[n]);
            float c1 = fmaxf(mv1[nj], s_max[n + 1]);
            g_tmax[(size_t)blockIdx.x * N_ + n]     = c0;
            g_tmax[(size_t)blockIdx.x * N_ + n + 1] = c1;
            atomicMax(&g_gmax_u[n],     fkey(c0));
            atomicMax(&g_gmax_u[n + 1], fkey(c1));
        }
    }
}

// ---------------- fused select + exact rescore + output ----------------------
__global__ __launch_bounds__(256)
void k_out(const float* __restrict__ X, const float* __restrict__ D,
           float* __restrict__ out) {
    __shared__ int   s_list[LMAX];
    __shared__ int   hm[HMAX];
    __shared__ float s_sc[HMAX];
    __shared__ float hw[HMAX];
    __shared__ int   s_nlist, s_cnt;
    const int n = blockIdx.x, tid = threadIdx.x;
    const int wid = tid >> 5, lane = tid & 31;

    if (tid == 0) { s_nlist = 0; s_cnt = 0; }
    __syncthreads();
    const float thr = funkey(g_gmax_u[n]) - THRESH;

    for (int b = tid; b < NTILE; b += 256) {
        if (g_tmax[(size_t)b * N_ + n] > thr) {
            int s = atomicAdd(&s_nlist, 1);
            if (s < LMAX) s_list[s] = b;
        }
    }
    __syncthreads();
    int nlist = s_nlist; if (nlist > LMAX) nlist = LMAX;

    const int nrows = nlist * 128;
    for (int r = tid; r < nrows; r += 256) {
        int m = s_list[r >> 7] * 128 + (r & 127);
        if (m < M_) {
            if (__bfloat162float(g_scores[(size_t)m * N_ + n]) > thr) {
                int s = atomicAdd(&s_cnt, 1);
                if (s < HMAX) hm[s] = m;
            }
        }
    }
    __syncthreads();
    int cnt = s_cnt; if (cnt > HMAX) cnt = HMAX;

    if (tid == 0) {            // sort by m -> deterministic order below
        for (int i = 1; i < cnt; i++) {
            int km = hm[i]; int j = i - 1;
            while (j >= 0 && hm[j] > km) { hm[j+1] = hm[j]; j--; }
            hm[j+1] = km;
        }
    }
    __syncthreads();

    // exact fp32 scores, one warp per candidate, float4 loads, fixed-tree sum
    const float4* xp4 = (const float4*)(X + (size_t)n * K_);
    for (int l = wid; l < cnt; l += 8) {
        const float4* dr4 = (const float4*)(D + (size_t)hm[l] * K_);
        float p = 0.f;
        #pragma unroll
        for (int q = 0; q < K_ / 128; q++) {     // 24 float4 per lane
            float4 xv = xp4[lane + q * 32];
            float4 dv = dr4[lane + q * 32];
            p += xv.x * dv.x + xv.y * dv.y + xv.z * dv.z + xv.w * dv.w;
        }
        #pragma unroll
        for (int mk = 16; mk > 0; mk >>= 1)
            p += __shfl_xor_sync(0xFFFFFFFFu, p, mk);
        if (lane == 0) s_sc[l] = p * INV_VAR;
    }
    __syncthreads();

    float gm = -1e30f;
    for (int l = 0; l < cnt; l++) gm = fmaxf(gm, s_sc[l]);
    if (tid < cnt) hw[tid] = expf(s_sc[tid] - gm);
    __syncthreads();
    float wsum = 0.f;
    for (int l = 0; l < cnt; l++) wsum += hw[l];
    const float inv = 1.0f / wsum;

    // output: skip negligible weights (< 1e-14 relative; deterministic)
    float4* out4 = (float4*)(out + (size_t)n * K_);
    #pragma unroll
    for (int q = 0; q < 3; q++) {
        int j4 = tid + q * 256;                  // 768 float4 = 3072 floats
        float4 a = make_float4(0.f, 0.f, 0.f, 0.f);
        for (int l = 0; l < cnt; l++) {
            float w = hw[l];
            if (w < 1e-14f) continue;
            float4 dv = ((const float4*)(D + (size_t)hm[l] * K_))[j4];
            a.x += w * dv.x; a.y += w * dv.y; a.z += w * dv.z; a.w += w * dv.w;
        }
        a.x *= inv; a.y *= inv; a.z *= inv; a.w *= inv;
        out4[j4] = a;
    }
}

// ---------------- launch ----------------
extern "C" void kernel_launch(void* const* d_in, const int* in_sizes, int n_in,
                              void* d_out, int out_size) {
    (void)in_sizes; (void)n_in; (void)out_size;
    const float* X = (const float*)d_in[0];
    const float* D = (const float*)d_in[1];
    float* out = (float*)d_out;

    cudaFuncSetAttribute(k_gemm1, cudaFuncAttributeMaxDynamicSharedMemorySize, NSTG * STG);

    k_conv_x<<<(N_ * K_ / 8 + 255) / 256, 256>>>(X);

    k_gemm1<<<(M_ + 127) / 128, 256, NSTG * STG>>>(D);

    k_out<<<N_, 256>>>(X, D, out);
}

// round 16
// speedup vs baseline: 1.9025x; 1.9025x over previous
#include <cuda_runtime.h>
#include <cuda_bf16.h>
#include <math.h>
#include <stdint.h>

#define N_     256
#define M_     50000
#define K_     3072
#define KT     64             // bf16 k per tile (128B rows, classic SW128)
#define NT1    (K_ / KT)      // 48
#define NTILE  391            // ceil(M/128)
#define INV_VAR 4.0f
#define HMAX   64
#define LMAX   64
#define THRESH 38.0f          // 30 (softmax support) + 8 (bf16 score + bf16 store margin)
#define STG    49152          // stage: A 16K | B 32K
#define NSTG   3

// ---------------- device scratch (allocation-free) ----------------
__device__ __align__(128) __nv_bfloat16  g_scores[(size_t)M_ * N_];
__device__ __align__(128) __nv_bfloat16  g_Xhi[(size_t)N_ * K_];
__device__ __align__(128) float          g_tmax[(size_t)NTILE * N_];
__device__ unsigned int g_gmax_u[N_];

// ---------------- helpers ----------------
__device__ __forceinline__ uint32_t s2u(const void* p) {
    return (uint32_t)__cvta_generic_to_shared(p);
}
// 128B rows, classic SW128: chunk c (16B) XOR row&7
__device__ __forceinline__ uint32_t soff64(uint32_t r, uint32_t c) {
    return (r << 7) + ((c ^ (r & 7)) << 4);
}
__device__ __forceinline__ void cp16(uint32_t dst, const void* src) {
    asm volatile("cp.async.cg.shared.global [%0], [%1], 16;" :: "r"(dst), "l"(src));
}
__device__ __forceinline__ void cp_commit() { asm volatile("cp.async.commit_group;"); }
__device__ __forceinline__ void cp_wait1() { asm volatile("cp.async.wait_group 1;" ::: "memory"); }
__device__ __forceinline__ void cp_wait0() { asm volatile("cp.async.wait_group 0;" ::: "memory"); }

__device__ __forceinline__ void ldsm4(uint32_t* d, uint32_t addr) {
    asm volatile("ldmatrix.sync.aligned.m8n8.x4.shared.b16 {%0,%1,%2,%3}, [%4];"
        : "=r"(d[0]), "=r"(d[1]), "=r"(d[2]), "=r"(d[3]) : "r"(addr));
}
__device__ __forceinline__ void mma_bf16(float* c, const uint32_t* a, uint32_t b0, uint32_t b1) {
    asm volatile("mma.sync.aligned.m16n8k16.row.col.f32.bf16.bf16.f32 "
        "{%0,%1,%2,%3}, {%4,%5,%6,%7}, {%8,%9}, {%0,%1,%2,%3};"
        : "+f"(c[0]), "+f"(c[1]), "+f"(c[2]), "+f"(c[3])
        : "r"(a[0]), "r"(a[1]), "r"(a[2]), "r"(a[3]), "r"(b0), "r"(b1));
}
__device__ __forceinline__ unsigned int fkey(float f) {
    unsigned int b = __float_as_uint(f);
    return (b & 0x80000000u) ? ~b : (b | 0x80000000u);
}
__device__ __forceinline__ float funkey(unsigned int k) {
    unsigned int b = (k & 0x80000000u) ? (k & 0x7FFFFFFFu) : ~k;
    return __uint_as_float(b);
}
__device__ __forceinline__ uint32_t pk2(float x, float y) {   // bf16(x) low, bf16(y) high
    __nv_bfloat162 t = __floats2bfloat162_rn(x, y);
    return *(uint32_t*)&t;
}

// ---------------- X fp32 -> bf16 (+ zero per-launch state in block 0) --------
__global__ __launch_bounds__(256)
void k_split_x(const float* __restrict__ X) {
    if (blockIdx.x == 0) g_gmax_u[threadIdx.x] = 0u;
    size_t i = (size_t)blockIdx.x * 256 + threadIdx.x;
    if (i >= (size_t)N_ * K_ / 4) return;
    float4 v = ((const float4*)X)[i];
    unsigned long long ph = (unsigned long long)pk2(v.x, v.y)
                          | ((unsigned long long)pk2(v.z, v.w) << 32);
    ((unsigned long long*)g_Xhi)[i] = ph;
}

// ---------------- GEMM1: approx scores[m][n] = 4 * bf16(D).bf16(X)^T ---------
// CTA tile 128m x 256n. 8 warps = 2m x 4n, warp tile 64x64. KT=64, 3-stage
// ring, prefetch distance 2. D read once (fp32), converted in-register.
// (exact R12 configuration -- measured best)
__global__ __launch_bounds__(256, 1)
void k_gemm1(const float* __restrict__ Dp) {
    extern __shared__ char smem[];
    const uint32_t sb = s2u(smem);
    const int tid = threadIdx.x, wid = tid >> 5, lane = tid & 31;
    const int m0 = blockIdx.x * 128;
    const int wm = (wid >> 2) * 64;        // 0 or 64
    const int wn = (wid & 3) * 64;         // 0,64,128,192

    const float* aPtr[2];
    uint32_t aOff[2][2];
    #pragma unroll
    for (int p = 0; p < 2; p++) {
        int e = tid + p * 256;
        int row = e >> 2, q = e & 3;
        int m = m0 + row; if (m >= M_) m = M_ - 1;
        aPtr[p] = Dp + (size_t)m * K_ + q * 16;
        aOff[p][0] = soff64(row, q * 2);
        aOff[p][1] = soff64(row, q * 2 + 1);
    }

    float acc[4][8][4];
    #pragma unroll
    for (int a = 0; a < 4; a++)
        #pragma unroll
        for (int b = 0; b < 8; b++)
            #pragma unroll
            for (int q = 0; q < 4; q++) acc[a][b][q] = 0.f;

    float4 fA[8];
    auto ldgA = [&](int kt) {
        #pragma unroll
        for (int p = 0; p < 2; p++) {
            const float* ptr = aPtr[p] + kt * KT;
            fA[p*4+0] = *(const float4*)(ptr);
            fA[p*4+1] = *(const float4*)(ptr + 4);
            fA[p*4+2] = *(const float4*)(ptr + 8);
            fA[p*4+3] = *(const float4*)(ptr + 12);
        }
    };
    auto stsA = [&](int s) {
        char* st = smem + s * STG;
        #pragma unroll
        for (int p = 0; p < 2; p++) {
            float4 a = fA[p*4+0], b = fA[p*4+1], c = fA[p*4+2], d = fA[p*4+3];
            uint4 h0, h1;
            h0.x = pk2(a.x, a.y); h0.y = pk2(a.z, a.w);
            h0.z = pk2(b.x, b.y); h0.w = pk2(b.z, b.w);
            h1.x = pk2(c.x, c.y); h1.y = pk2(c.z, c.w);
            h1.z = pk2(d.x, d.y); h1.w = pk2(d.z, d.w);
            *(uint4*)(st + aOff[p][0]) = h0;
            *(uint4*)(st + aOff[p][1]) = h1;
        }
    };
    auto cpB = [&](int s, int kt) {
        const uint32_t st = sb + s * STG + 16384;
        const int k0 = kt * KT;
        #pragma unroll
        for (int q8 = 0; q8 < 8; q8++) {
            int e = q8 * 256 + tid;
            int r = e >> 3, c = e & 7;
            cp16(st + soff64(r, c), g_Xhi + (size_t)r * K_ + k0 + c * 8);
        }
        cp_commit();
    };

    ldgA(0); cpB(0, 0); stsA(0);
    ldgA(1); cpB(1, 1); stsA(1);

    for (int t = 0; t < NT1; t++) {
        const int pf = (t + 2 < NT1);
        if (pf) ldgA(t + 2);
        if (pf) cp_wait1(); else cp_wait0();
        __syncthreads();
        const int sNew = (t + 2) % NSTG;
        if (pf) cpB(sNew, t + 2);

        const uint32_t stA = sb + (t % NSTG) * STG;
        const uint32_t stB = stA + 16384;
        #pragma unroll
        for (int ks = 0; ks < 4; ks++) {
            const uint32_t cc = ks * 2 + (lane >> 4);
            uint32_t ah[4][4];
            #pragma unroll
            for (int mi = 0; mi < 4; mi++)
                ldsm4(ah[mi], stA + soff64(wm + mi * 16 + (lane & 15), cc));
            #pragma unroll
            for (int g = 0; g < 4; g++) {
                uint32_t bh[4];
                ldsm4(bh, stB + soff64(wn + g * 16 + (lane & 15), cc));
                #pragma unroll
                for (int mi = 0; mi < 4; mi++) {
                    mma_bf16(acc[mi][g*2],   ah[mi], bh[0], bh[2]);
                    mma_bf16(acc[mi][g*2+1], ah[mi], bh[1], bh[3]);
                }
            }
        }
        if (pf) stsA(sNew);
    }

    // epilogue: scale, store bf16 scores, per-n maxima
    float mv0[8], mv1[8];
    #pragma unroll
    for (int mi = 0; mi < 4; mi++) {
        int m = m0 + wm + mi * 16 + (lane >> 2);
        #pragma unroll
        for (int nj = 0; nj < 8; nj++) {
            int n = wn + nj * 8 + (lane & 3) * 2;
            float v0 = acc[mi][nj][0] * INV_VAR, v1 = acc[mi][nj][1] * INV_VAR;
            float v2 = acc[mi][nj][2] * INV_VAR, v3 = acc[mi][nj][3] * INV_VAR;
            acc[mi][nj][0] = v0; acc[mi][nj][1] = v1;
            acc[mi][nj][2] = v2; acc[mi][nj][3] = v3;
            if (m < M_)     *(uint32_t*)&g_scores[(size_t)m * N_ + n]       = pk2(v0, v1);
            if (m + 8 < M_) *(uint32_t*)&g_scores[(size_t)(m + 8) * N_ + n] = pk2(v2, v3);
        }
    }
    #pragma unroll
    for (int nj = 0; nj < 8; nj++) {
        float v0 = -1e30f, v1 = -1e30f;
        #pragma unroll
        for (int mi = 0; mi < 4; mi++) {
            v0 = fmaxf(v0, fmaxf(acc[mi][nj][0], acc[mi][nj][2]));
            v1 = fmaxf(v1, fmaxf(acc[mi][nj][1], acc[mi][nj][3]));
        }
        #pragma unroll
        for (int mk = 4; mk < 32; mk <<= 1) {
            v0 = fmaxf(v0, __shfl_xor_sync(0xFFFFFFFFu, v0, mk));
            v1 = fmaxf(v1, __shfl_xor_sync(0xFFFFFFFFu, v1, mk));
        }
        mv0[nj] = v0; mv1[nj] = v1;
    }
    float* s_max = (float*)smem;          // stage-0 A region dead after final barrier
    __syncthreads();
    if (wm == 0 && (lane >> 2) == 0) {
        #pragma unroll
        for (int nj = 0; nj < 8; nj++) {
            int n = wn + nj * 8 + (lane & 3) * 2;
            s_max[n] = mv0[nj]; s_max[n + 1] = mv1[nj];
        }
    }
    __syncthreads();
    if (wm == 64 && (lane >> 2) == 0) {
        #pragma unroll
        for (int nj = 0; nj < 8; nj++) {
            int n = wn + nj * 8 + (lane & 3) * 2;
            float c0 = fmaxf(mv0[nj], s_max[n]);
            float c1 = fmaxf(mv1[nj], s_max[n + 1]);
            g_tmax[(size_t)blockIdx.x * N_ + n]     = c0;
            g_tmax[(size_t)blockIdx.x * N_ + n + 1] = c1;
            atomicMax(&g_gmax_u[n],     fkey(c0));
            atomicMax(&g_gmax_u[n + 1], fkey(c1));
        }
    }
}

// ---------------- fused select + exact rescore + output (512 threads) --------
__global__ __launch_bounds__(512)
void k_out(const float* __restrict__ X, const float* __restrict__ D,
           float* __restrict__ out) {
    __shared__ int   s_list[LMAX];
    __shared__ int   hm[HMAX];
    __shared__ float s_sc[HMAX];
    __shared__ float hw[HMAX];
    __shared__ int   s_nlist, s_cnt;
    const int n = blockIdx.x, tid = threadIdx.x;
    const int wid = tid >> 5, lane = tid & 31;

    if (tid == 0) { s_nlist = 0; s_cnt = 0; }
    __syncthreads();
    const float thr = funkey(g_gmax_u[n]) - THRESH;

    // phase 1: hot tiles (391 loads over 512 threads -> 1 round-trip)
    if (tid < NTILE) {
        if (g_tmax[(size_t)tid * N_ + n] > thr) {
            int s = atomicAdd(&s_nlist, 1);
            if (s < LMAX) s_list[s] = tid;
        }
    }
    __syncthreads();
    int nlist = s_nlist; if (nlist > LMAX) nlist = LMAX;

    // phase 2: rows of hot tiles, one load per thread
    const int nrows = nlist * 128;
    for (int r = tid; r < nrows; r += 512) {
        int m = s_list[r >> 7] * 128 + (r & 127);
        if (m < M_) {
            if (__bfloat162float(g_scores[(size_t)m * N_ + n]) > thr) {
                int s = atomicAdd(&s_cnt, 1);
                if (s < HMAX) hm[s] = m;
            }
        }
    }
    __syncthreads();
    int cnt = s_cnt; if (cnt > HMAX) cnt = HMAX;

    if (tid == 0) {            // sort by m -> deterministic order below
        for (int i = 1; i < cnt; i++) {
            int km = hm[i]; int j = i - 1;
            while (j >= 0 && hm[j] > km) { hm[j+1] = hm[j]; j--; }
            hm[j+1] = km;
        }
    }
    __syncthreads();

    // phase 3: exact fp32 scores, one warp per candidate, float4 loads
    const float4* xp4 = (const float4*)(X + (size_t)n * K_);
    for (int l = wid; l < cnt; l += 16) {
        const float4* dr4 = (const float4*)(D + (size_t)hm[l] * K_);
        float p = 0.f;
        #pragma unroll
        for (int q = 0; q < K_ / 128; q++) {     // 24 float4 per lane
            float4 xv = xp4[lane + q * 32];
            float4 dv = dr4[lane + q * 32];
            p += xv.x * dv.x + xv.y * dv.y + xv.z * dv.z + xv.w * dv.w;
        }
        #pragma unroll
        for (int mk = 16; mk > 0; mk >>= 1)
            p += __shfl_xor_sync(0xFFFFFFFFu, p, mk);
        if (lane == 0) s_sc[l] = p * INV_VAR;
    }
    __syncthreads();

    // phase 4: exact softmax over candidates
    float gm = -1e30f;
    for (int l = 0; l < cnt; l++) gm = fmaxf(gm, s_sc[l]);
    if (tid < cnt) hw[tid] = expf(s_sc[tid] - gm);
    __syncthreads();
    float wsum = 0.f;
    for (int l = 0; l < cnt; l++) wsum += hw[l];
    const float inv = 1.0f / wsum;

    // phase 5: output, float4, skip negligible weights (deterministic)
    float4* out4 = (float4*)(out + (size_t)n * K_);
    #pragma unroll
    for (int q = 0; q < 2; q++) {
        int j4 = tid + q * 512;                  // 768 float4 total
        if (j4 >= K_ / 4) break;
        float4 a = make_float4(0.f, 0.f, 0.f, 0.f);
        for (int l = 0; l < cnt; l++) {
            float w = hw[l];
            if (w < 1e-14f) continue;
            float4 dv = ((const float4*)(D + (size_t)hm[l] * K_))[j4];
            a.x += w * dv.x; a.y += w * dv.y; a.z += w * dv.z; a.w += w * dv.w;
        }
        a.x *= inv; a.y *= inv; a.z *= inv; a.w *= inv;
        out4[j4] = a;
    }
}

// ---------------- launch ----------------
extern "C" void kernel_launch(void* const* d_in, const int* in_sizes, int n_in,
                              void* d_out, int out_size) {
    (void)in_sizes; (void)n_in; (void)out_size;
    const float* X = (const float*)d_in[0];
    const float* D = (const float*)d_in[1];
    float* out = (float*)d_out;

    cudaFuncSetAttribute(k_gemm1, cudaFuncAttributeMaxDynamicSharedMemorySize, NSTG * STG);

    k_split_x<<<(N_ * K_ / 4 + 255) / 256, 256>>>(X);

    k_gemm1<<<(M_ + 127) / 128, 256, NSTG * STG>>>(D);

    k_out<<<N_, 512>>>(X, D, out);
}